// round 5
// baseline (speedup 1.0000x reference)
#include <cuda_runtime.h>
#include <cstdint>

#define DFI __device__ __forceinline__
typedef unsigned long long u64;

DFI float fsig(float x)  { return __fdividef(1.f, 1.f + __expf(-x)); }
DFI float ftanh(float x) { float e = __expf(2.f * x); return 1.f - __fdividef(2.f, e + 1.f); }
DFI float lrelu(float x) { return x > 0.f ? x : 0.01f * x; }

DFI u64 lds64(const float* p) { return *reinterpret_cast<const u64*>(p); }
DFI u64 pk0(float lo) { u64 r; asm("mov.b64 %0,{%1,%2};" : "=l"(r) : "f"(lo), "f"(0.f)); return r; }
DFI float red2(u64 v) { float lo, hi; asm("mov.b64 {%0,%1},%2;" : "=f"(lo), "=f"(hi) : "l"(v)); return lo + hi; }
DFI u64 ffma2(u64 a, u64 b, u64 c) { u64 d; asm("fma.rn.f32x2 %0,%1,%2,%3;" : "=l"(d) : "l"(a), "l"(b), "l"(c)); return d; }

// ---------------- scratch (no dynamic allocation allowed) ----------------
__device__ float g_hlast[10240 * 64];
__device__ float g_ssrc[10240];
__device__ float g_sdst[10240];
__device__ float g_hatt[10240 * 64];
__device__ float g_hfc[10240 * 64];
__device__ float g_z[512 * 20 * 64];
__device__ float g_r[512 * 20 * 64];

// =========================================================================
// Fused 2-layer GRU, 8 seqs/warp, gate-split passes, FFMA2 + 16B smem loads.
// Weight layouts in smem:
//   pair-pack (Wih0 only): wp[k2*384 + 2*o + {0,1}] = W[o][2k2+{0,1}]
//   quad-pack (64-wide mats): wq[k4*768 + 4*o + q] = W[o][4k4+q]
// Lane owns outputs o = lane, lane+32 (per gate). Pass A reduces r,z rows
// (o in [0,128)), pass B reduces n rows (o in [128,192)). z parked in smem,
// r carried in registers between passes.
// =========================================================================
template <int DIN, bool STORE_ALL, int WARPS>
__global__ void __launch_bounds__(WARPS * 32, 1) gru2q_kernel(
    const float* __restrict__ X,
    const float* __restrict__ Wih0, const float* __restrict__ Whh0,
    const float* __restrict__ bih0, const float* __restrict__ bhh0,
    const float* __restrict__ Wih1, const float* __restrict__ Whh1,
    const float* __restrict__ bih1, const float* __restrict__ bhh1,
    float* __restrict__ OUT, int N, int T)
{
    extern __shared__ float sm[];
    const int SPB = WARPS * 8;
    float* wih0p = sm;                          // DIN*192
    float* whh0q = wih0p + DIN * 192;           // 12288
    float* wih1q = whh0q + 12288;               // 12288
    float* whh1q = wih1q + 12288;               // 12288
    float* sb    = whh1q + 12288;               // 512
    float* sh0   = sb + 512;                    // SPB*64
    float* sh1   = sh0 + SPB * 64;              // SPB*64
    float* sx    = sh1 + SPB * 64;              // SPB*DIN
    float* srz   = sx + SPB * DIN;              // WARPS*512

    const int tid = threadIdx.x, nth = WARPS * 32;
    for (int i = tid; i < (DIN / 2) * 192; i += nth) {
        int k2 = i / 192, o = i - k2 * 192;
        wih0p[k2 * 384 + 2 * o]     = Wih0[o * DIN + 2 * k2];
        wih0p[k2 * 384 + 2 * o + 1] = Wih0[o * DIN + 2 * k2 + 1];
    }
    for (int i = tid; i < 16 * 192; i += nth) {
        int k4 = i / 192, o = i - k4 * 192;
        int dst = k4 * 768 + 4 * o, src = o * 64 + 4 * k4;
#pragma unroll
        for (int q = 0; q < 4; q++) {
            whh0q[dst + q] = Whh0[src + q];
            wih1q[dst + q] = Wih1[src + q];
            whh1q[dst + q] = Whh1[src + q];
        }
    }
    for (int i = tid; i < 128; i += nth) { sb[i] = bih0[i] + bhh0[i]; sb[256 + i] = bih1[i] + bhh1[i]; }
    for (int i = tid; i < 64; i += nth) {
        sb[128 + i] = bih0[128 + i]; sb[192 + i] = bhh0[128 + i];
        sb[384 + i] = bih1[128 + i]; sb[448 + i] = bhh1[128 + i];
    }
    for (int i = tid; i < SPB * 64; i += nth) { sh0[i] = 0.f; sh1[i] = 0.f; }
    __syncthreads();

    const int w = tid >> 5, lane = tid & 31;
    const int sl = w * 8;
    const int sg = (int)blockIdx.x * SPB + sl;
    if (sg >= N) return;

    int oqA[4], woA[4];
#pragma unroll
    for (int j = 0; j < 4; j++) {
        int o = lane + ((j & 1) << 5) + ((j >> 1) << 6);
        oqA[j] = 4 * o; woA[j] = 2 * o;
    }
    int oqB[2], woB[2];
#pragma unroll
    for (int u = 0; u < 2; u++) { int o = 128 + lane + (u << 5); oqB[u] = 4 * o; woB[u] = 2 * o; }

    float* sxw  = sx + w * 8 * DIN;
    float* srzw = srz + w * 512;
    float* sh0w = sh0 + sl * 64;
    float* sh1w = sh1 + sl * 64;
    const float* Xb = X + (long long)sg * T * DIN;

    for (int t = 0; t < T; ++t) {
        // stage x_t for the warp's 8 sequences
        for (int i = lane; i < 8 * DIN; i += 32) {
            int s = i / DIN, d = i - s * DIN;
            sxw[i] = Xb[(long long)s * T * DIN + t * DIN + d];
        }
        __syncwarp();

        float rr[8][2];

        // ========================= LAYER 0 =========================
        {   // ---- pass A: r,z ----
            u64 cz[8][4];
#pragma unroll
            for (int s = 0; s < 8; s++)
#pragma unroll
                for (int j = 0; j < 4; j++) cz[s][j] = pk0(sb[(oqA[j] >> 2)]);
            // x part (pair loop)
#pragma unroll
            for (int k2 = 0; k2 < DIN / 2; k2++) {
                const float* wb = wih0p + k2 * 384;
                u64 wv[4];
#pragma unroll
                for (int j = 0; j < 4; j++) wv[j] = lds64(wb + woA[j]);
#pragma unroll
                for (int s = 0; s < 8; s++) {
                    u64 x2 = lds64(sxw + s * DIN + 2 * k2);
#pragma unroll
                    for (int j = 0; j < 4; j++) cz[s][j] = ffma2(wv[j], x2, cz[s][j]);
                }
            }
            // h part (quad loop)
#pragma unroll 1
            for (int k4 = 0; k4 < 16; k4++) {
                const float* wb = whh0q + k4 * 768;
                ulonglong2 wv[4];
#pragma unroll
                for (int j = 0; j < 4; j++) wv[j] = *reinterpret_cast<const ulonglong2*>(wb + oqA[j]);
#pragma unroll
                for (int s = 0; s < 8; s++) {
                    ulonglong2 h2 = *reinterpret_cast<const ulonglong2*>(sh0w + s * 64 + 4 * k4);
#pragma unroll
                    for (int j = 0; j < 4; j++) {
                        cz[s][j] = ffma2(wv[j].x, h2.x, cz[s][j]);
                        cz[s][j] = ffma2(wv[j].y, h2.y, cz[s][j]);
                    }
                }
            }
#pragma unroll
            for (int s = 0; s < 8; s++)
#pragma unroll
                for (int u = 0; u < 2; u++) {
                    rr[s][u] = fsig(red2(cz[s][u]));
                    srzw[(s * 2 + u) * 32 + lane] = fsig(red2(cz[s][2 + u]));
                }
        }
        {   // ---- pass B: n + combine ----
            u64 an[8][2], hn[8][2];
#pragma unroll
            for (int s = 0; s < 8; s++)
#pragma unroll
                for (int u = 0; u < 2; u++) {
                    an[s][u] = pk0(sb[128 + lane + (u << 5)]);
                    hn[s][u] = pk0(sb[192 + lane + (u << 5)]);
                }
#pragma unroll
            for (int k2 = 0; k2 < DIN / 2; k2++) {
                const float* wb = wih0p + k2 * 384;
                u64 wv0 = lds64(wb + woB[0]), wv1 = lds64(wb + woB[1]);
#pragma unroll
                for (int s = 0; s < 8; s++) {
                    u64 x2 = lds64(sxw + s * DIN + 2 * k2);
                    an[s][0] = ffma2(wv0, x2, an[s][0]);
                    an[s][1] = ffma2(wv1, x2, an[s][1]);
                }
            }
#pragma unroll 1
            for (int k4 = 0; k4 < 16; k4++) {
                const float* wb = whh0q + k4 * 768;
                ulonglong2 wv0 = *reinterpret_cast<const ulonglong2*>(wb + oqB[0]);
                ulonglong2 wv1 = *reinterpret_cast<const ulonglong2*>(wb + oqB[1]);
#pragma unroll
                for (int s = 0; s < 8; s++) {
                    ulonglong2 h2 = *reinterpret_cast<const ulonglong2*>(sh0w + s * 64 + 4 * k4);
                    hn[s][0] = ffma2(wv0.x, h2.x, hn[s][0]);
                    hn[s][0] = ffma2(wv0.y, h2.y, hn[s][0]);
                    hn[s][1] = ffma2(wv1.x, h2.x, hn[s][1]);
                    hn[s][1] = ffma2(wv1.y, h2.y, hn[s][1]);
                }
            }
            __syncwarp();
#pragma unroll
            for (int s = 0; s < 8; s++)
#pragma unroll
                for (int u = 0; u < 2; u++) {
                    float n = ftanh(fmaf(rr[s][u], red2(hn[s][u]), red2(an[s][u])));
                    float z = srzw[(s * 2 + u) * 32 + lane];
                    int hi = s * 64 + lane + (u << 5);
                    float hold = sh0w[hi];
                    sh0w[hi] = (1.f - z) * n + z * hold;
                }
            __syncwarp();
        }

        // ========================= LAYER 1 =========================
        {   // ---- pass A: r,z ----
            u64 cz[8][4];
#pragma unroll
            for (int s = 0; s < 8; s++)
#pragma unroll
                for (int j = 0; j < 4; j++) cz[s][j] = pk0(sb[256 + (oqA[j] >> 2)]);
#pragma unroll 1
            for (int k4 = 0; k4 < 16; k4++) {
                {   // ih part (input = new sh0)
                    const float* wb = wih1q + k4 * 768;
                    ulonglong2 wv[4];
#pragma unroll
                    for (int j = 0; j < 4; j++) wv[j] = *reinterpret_cast<const ulonglong2*>(wb + oqA[j]);
#pragma unroll
                    for (int s = 0; s < 8; s++) {
                        ulonglong2 x2 = *reinterpret_cast<const ulonglong2*>(sh0w + s * 64 + 4 * k4);
#pragma unroll
                        for (int j = 0; j < 4; j++) {
                            cz[s][j] = ffma2(wv[j].x, x2.x, cz[s][j]);
                            cz[s][j] = ffma2(wv[j].y, x2.y, cz[s][j]);
                        }
                    }
                }
                {   // hh part
                    const float* wb = whh1q + k4 * 768;
                    ulonglong2 wv[4];
#pragma unroll
                    for (int j = 0; j < 4; j++) wv[j] = *reinterpret_cast<const ulonglong2*>(wb + oqA[j]);
#pragma unroll
                    for (int s = 0; s < 8; s++) {
                        ulonglong2 h2 = *reinterpret_cast<const ulonglong2*>(sh1w + s * 64 + 4 * k4);
#pragma unroll
                        for (int j = 0; j < 4; j++) {
                            cz[s][j] = ffma2(wv[j].x, h2.x, cz[s][j]);
                            cz[s][j] = ffma2(wv[j].y, h2.y, cz[s][j]);
                        }
                    }
                }
            }
#pragma unroll
            for (int s = 0; s < 8; s++)
#pragma unroll
                for (int u = 0; u < 2; u++) {
                    rr[s][u] = fsig(red2(cz[s][u]));
                    srzw[(s * 2 + u) * 32 + lane] = fsig(red2(cz[s][2 + u]));
                }
        }
        {   // ---- pass B: n + combine ----
            u64 an[8][2], hn[8][2];
#pragma unroll
            for (int s = 0; s < 8; s++)
#pragma unroll
                for (int u = 0; u < 2; u++) {
                    an[s][u] = pk0(sb[384 + lane + (u << 5)]);
                    hn[s][u] = pk0(sb[448 + lane + (u << 5)]);
                }
#pragma unroll 1
            for (int k4 = 0; k4 < 16; k4++) {
                const float* bi = wih1q + k4 * 768;
                const float* bh = whh1q + k4 * 768;
                ulonglong2 wi0 = *reinterpret_cast<const ulonglong2*>(bi + oqB[0]);
                ulonglong2 wi1 = *reinterpret_cast<const ulonglong2*>(bi + oqB[1]);
                ulonglong2 wh0 = *reinterpret_cast<const ulonglong2*>(bh + oqB[0]);
                ulonglong2 wh1 = *reinterpret_cast<const ulonglong2*>(bh + oqB[1]);
#pragma unroll
                for (int s = 0; s < 8; s++) {
                    ulonglong2 x2 = *reinterpret_cast<const ulonglong2*>(sh0w + s * 64 + 4 * k4);
                    ulonglong2 h2 = *reinterpret_cast<const ulonglong2*>(sh1w + s * 64 + 4 * k4);
                    an[s][0] = ffma2(wi0.x, x2.x, an[s][0]);
                    an[s][0] = ffma2(wi0.y, x2.y, an[s][0]);
                    an[s][1] = ffma2(wi1.x, x2.x, an[s][1]);
                    an[s][1] = ffma2(wi1.y, x2.y, an[s][1]);
                    hn[s][0] = ffma2(wh0.x, h2.x, hn[s][0]);
                    hn[s][0] = ffma2(wh0.y, h2.y, hn[s][0]);
                    hn[s][1] = ffma2(wh1.x, h2.x, hn[s][1]);
                    hn[s][1] = ffma2(wh1.y, h2.y, hn[s][1]);
                }
            }
            __syncwarp();
#pragma unroll
            for (int s = 0; s < 8; s++)
#pragma unroll
                for (int u = 0; u < 2; u++) {
                    float n = ftanh(fmaf(rr[s][u], red2(hn[s][u]), red2(an[s][u])));
                    float z = srzw[(s * 2 + u) * 32 + lane];
                    int hi = s * 64 + lane + (u << 5);
                    float hold = sh1w[hi];
                    float hnew = (1.f - z) * n + z * hold;
                    sh1w[hi] = hnew;
                    if (STORE_ALL) OUT[((long long)(sg + s) * T + t) * 64 + lane + (u << 5)] = hnew;
                }
            __syncwarp();
        }
    }
    if (!STORE_ALL) {
#pragma unroll
        for (int s = 0; s < 8; s++)
#pragma unroll
            for (int u = 0; u < 2; u++)
                OUT[(long long)(sg + s) * 64 + lane + (u << 5)] = sh1w[s * 64 + lane + (u << 5)];
    }
}

// =========================================================================
// xp = h @ trans_W.T + trans_b ; s_dst = xp @ a[:64] ; s_src = xp @ a[64:]
// =========================================================================
__global__ void trans_score_kernel(const float* __restrict__ H,
    const float* __restrict__ W, const float* __restrict__ b,
    const float* __restrict__ a, float* __restrict__ ssrc,
    float* __restrict__ sdst, int Nrows)
{
    __shared__ float sW[4096], sbv[64], sad[64], sas[64];
    for (int i = threadIdx.x; i < 4096; i += blockDim.x) sW[i] = W[i];
    for (int i = threadIdx.x; i < 64; i += blockDim.x) { sbv[i] = b[i]; sad[i] = a[i]; sas[i] = a[64 + i]; }
    __syncthreads();
    for (int row = blockIdx.x * blockDim.x + threadIdx.x; row < Nrows; row += gridDim.x * blockDim.x) {
        float h[64];
        const float4* hp = (const float4*)(H + (long long)row * 64);
#pragma unroll
        for (int q = 0; q < 16; q++) { float4 v = hp[q]; h[4*q] = v.x; h[4*q+1] = v.y; h[4*q+2] = v.z; h[4*q+3] = v.w; }
        float sd = 0.f, ss = 0.f;
#pragma unroll 4
        for (int o = 0; o < 64; o++) {
            float acc = sbv[o];
#pragma unroll
            for (int k = 0; k < 64; k++) acc = fmaf(h[k], sW[o * 64 + k], acc);
            sd = fmaf(acc, sad[o], sd);
            ss = fmaf(acc, sas[o], ss);
        }
        sdst[row] = sd; ssrc[row] = ss;
    }
}

// =========================================================================
// Dense per-group GAT: out[i] = softmax_j(lrelu(ssrc[i]+sdst[j])) @ h + h[i]
// =========================================================================
__global__ void gat_att_kernel(const float* __restrict__ Hin,
    const float* __restrict__ ssrc, const float* __restrict__ sdst,
    float* __restrict__ Hout)
{
    __shared__ float sd[512];
    __shared__ float se[8][512];
    const int g = blockIdx.x >> 3, chunk = blockIdx.x & 7;
    for (int i = threadIdx.x; i < 512; i += blockDim.x) sd[i] = sdst[g * 512 + i];
    __syncthreads();
    const int w = threadIdx.x >> 5, lane = threadIdx.x & 31;
    const float* Hg = Hin + (long long)g * 512 * 64;
    for (int rr = 0; rr < 8; ++rr) {
        const int i = chunk * 64 + w * 8 + rr;
        const float si = ssrc[g * 512 + i];
        float m = -1e30f, sc[16];
#pragma unroll
        for (int jj = 0; jj < 16; jj++) {
            float v = lrelu(si + sd[lane + (jj << 5)]);
            sc[jj] = v; m = fmaxf(m, v);
        }
#pragma unroll
        for (int off = 16; off; off >>= 1) m = fmaxf(m, __shfl_xor_sync(~0u, m, off));
        float ssum = 0.f;
#pragma unroll
        for (int jj = 0; jj < 16; jj++) {
            float e = __expf(sc[jj] - m);
            se[w][lane + (jj << 5)] = e; ssum += e;
        }
#pragma unroll
        for (int off = 16; off; off >>= 1) ssum += __shfl_xor_sync(~0u, ssum, off);
        __syncwarp();
        float2 acc = make_float2(0.f, 0.f);
        const int c = lane << 1;
#pragma unroll 4
        for (int j = 0; j < 512; j++) {
            float e = se[w][j];
            float2 hv = *(const float2*)(Hg + j * 64 + c);
            acc.x = fmaf(e, hv.x, acc.x);
            acc.y = fmaf(e, hv.y, acc.y);
        }
        float inv = __fdividef(1.f, ssum);
        float2 hi = *(const float2*)(Hg + i * 64 + c);
        float2 res; res.x = fmaf(acc.x, inv, hi.x); res.y = fmaf(acc.y, inv, hi.y);
        *(float2*)(Hout + ((long long)g * 512 + i) * 64 + c) = res;
        __syncwarp();
    }
}

// ============================ fc: 64x64 linear ===========================
__global__ void fc_kernel(const float* __restrict__ IN, const float* __restrict__ W,
                          const float* __restrict__ b, float* __restrict__ O, int Nrows)
{
    __shared__ float sW[4096], sb2[64];
    for (int i = threadIdx.x; i < 4096; i += blockDim.x) sW[i] = W[i];
    for (int i = threadIdx.x; i < 64; i += blockDim.x) sb2[i] = b[i];
    __syncthreads();
    for (int row = blockIdx.x * blockDim.x + threadIdx.x; row < Nrows; row += gridDim.x * blockDim.x) {
        float h[64];
        const float4* hp = (const float4*)(IN + (long long)row * 64);
#pragma unroll
        for (int q = 0; q < 16; q++) { float4 v = hp[q]; h[4*q] = v.x; h[4*q+1] = v.y; h[4*q+2] = v.z; h[4*q+3] = v.w; }
        float* op = O + (long long)row * 64;
#pragma unroll 2
        for (int o = 0; o < 64; o++) {
            float acc = sb2[o];
#pragma unroll
            for (int k = 0; k < 64; k++) acc = fmaf(h[k], sW[o * 64 + k], acc);
            op[o] = acc;
        }
    }
}

// ============= z = tanh(permute(hfc) @ al_in_W.T + al_in_b) ==============
__global__ void z_kernel(const float* __restrict__ Hfc, const float* __restrict__ W,
                         const float* __restrict__ b, float* __restrict__ Z)
{
    __shared__ float sW[4096], sb2[64];
    for (int i = threadIdx.x; i < 4096; i += blockDim.x) sW[i] = W[i];
    for (int i = threadIdx.x; i < 64; i += blockDim.x) sb2[i] = b[i];
    __syncthreads();
    int r = blockIdx.x * blockDim.x + threadIdx.x;
    if (r >= 512 * 20) return;
    int i = r / 20, k = r - i * 20;
    const float* hp = Hfc + (long long)(k * 512 + i) * 64;
    float h[64];
#pragma unroll
    for (int q = 0; q < 16; q++) { float4 v = ((const float4*)hp)[q]; h[4*q] = v.x; h[4*q+1] = v.y; h[4*q+2] = v.z; h[4*q+3] = v.w; }
    float* op = Z + (long long)r * 64;
#pragma unroll 2
    for (int o = 0; o < 64; o++) {
        float acc = sb2[o];
#pragma unroll
        for (int kk = 0; kk < 64; kk++) acc = fmaf(h[kk], sW[o * 64 + kk], acc);
        op[o] = ftanh(acc);
    }
}

// ======================= ALSTM attention head ============================
__global__ void alstm_head_kernel(const float* __restrict__ R,
    const float* __restrict__ W1, const float* __restrict__ b1,
    const float* __restrict__ W2, const float* __restrict__ Wout,
    const float* __restrict__ bout, float* __restrict__ outv)
{
    __shared__ float sW1t[64 * 32], sb1[32], sW2[32], sWo[128];
    __shared__ float sr[8][64], ssk[8][20];
    for (int i = threadIdx.x; i < 2048; i += blockDim.x) { int d = i >> 5, o = i & 31; sW1t[i] = W1[o * 64 + d]; }
    if (threadIdx.x < 32) { sb1[threadIdx.x] = b1[threadIdx.x]; sW2[threadIdx.x] = W2[threadIdx.x]; }
    for (int i = threadIdx.x; i < 128; i += blockDim.x) sWo[i] = Wout[i];
    __syncthreads();
    const int w = threadIdx.x >> 5, lane = threadIdx.x & 31;
    const int i = blockIdx.x * 8 + w;
    const float* Ri = R + (long long)i * 20 * 64;
    for (int k = 0; k < 20; k++) {
        sr[w][lane] = Ri[k * 64 + lane];
        sr[w][lane + 32] = Ri[k * 64 + lane + 32];
        __syncwarp();
        float acc = sb1[lane];
#pragma unroll
        for (int d = 0; d < 64; d++) acc = fmaf(sr[w][d], sW1t[(d << 5) + lane], acc);
        float p = ftanh(acc) * sW2[lane];
#pragma unroll
        for (int off = 16; off; off >>= 1) p += __shfl_xor_sync(~0u, p, off);
        if (lane == 0) ssk[w][k] = p;
        __syncwarp();
    }
    float m = -1e30f;
    for (int k = 0; k < 20; k++) m = fmaxf(m, ssk[w][k]);
    float ssum = 0.f;
    for (int k = 0; k < 20; k++) ssum += __expf(ssk[w][k] - m);
    float inv = __fdividef(1.f, ssum);
    float accf = 0.f;
    for (int k = 0; k < 20; k++) {
        float ak = __expf(ssk[w][k] - m) * inv;
        float r1 = Ri[k * 64 + lane], r2 = Ri[k * 64 + lane + 32];
        accf = fmaf(ak * r1, sWo[64 + lane], accf);
        accf = fmaf(ak * r2, sWo[96 + lane], accf);
    }
    {
        float r1 = Ri[19 * 64 + lane], r2 = Ri[19 * 64 + lane + 32];
        accf = fmaf(r1, sWo[lane], accf);
        accf = fmaf(r2, sWo[32 + lane], accf);
    }
#pragma unroll
    for (int off = 16; off; off >>= 1) accf += __shfl_xor_sync(~0u, accf, off);
    if (lane == 0) outv[i] = accf + bout[0];
}

// ============ pred = lrelu(hfc[group 19]) @ fco_W.T + fco_b ==============
__global__ void pred_kernel(const float* __restrict__ Hfc, const float* __restrict__ fcoW,
                            const float* __restrict__ fcob, float* __restrict__ outv)
{
    __shared__ float sw[64];
    if (threadIdx.x < 64) sw[threadIdx.x] = fcoW[threadIdx.x];
    __syncthreads();
    int i = blockIdx.x * blockDim.x + threadIdx.x;
    if (i < 512) {
        const float* hp = Hfc + (long long)(19 * 512 + i) * 64;
        float s = fcob[0];
#pragma unroll 8
        for (int c = 0; c < 64; c++) { float v = hp[c]; v = v > 0.f ? v : 0.01f * v; s = fmaf(v, sw[c], s); }
        outv[512 + i] = s;
    }
}

// =========================================================================
extern "C" void kernel_launch(void* const* d_in, const int* in_sizes, int n_in,
                              void* d_out, int out_size)
{
    const float* x        = (const float*)d_in[0];
    const float* rWih0    = (const float*)d_in[1];
    const float* rWhh0    = (const float*)d_in[2];
    const float* rbih0    = (const float*)d_in[3];
    const float* rbhh0    = (const float*)d_in[4];
    const float* rWih1    = (const float*)d_in[5];
    const float* rWhh1    = (const float*)d_in[6];
    const float* rbih1    = (const float*)d_in[7];
    const float* rbhh1    = (const float*)d_in[8];
    const float* trans_W  = (const float*)d_in[9];
    const float* trans_b  = (const float*)d_in[10];
    const float* a_vec    = (const float*)d_in[11];
    const float* fc_W     = (const float*)d_in[12];
    const float* fc_b     = (const float*)d_in[13];
    const float* fco_W    = (const float*)d_in[14];
    const float* fco_b    = (const float*)d_in[15];
    const float* al_in_W  = (const float*)d_in[16];
    const float* al_in_b  = (const float*)d_in[17];
    const float* aWih0    = (const float*)d_in[18];
    const float* aWhh0    = (const float*)d_in[19];
    const float* abih0    = (const float*)d_in[20];
    const float* abhh0    = (const float*)d_in[21];
    const float* aWih1    = (const float*)d_in[22];
    const float* aWhh1    = (const float*)d_in[23];
    const float* abih1    = (const float*)d_in[24];
    const float* abhh1    = (const float*)d_in[25];
    const float* att1_W   = (const float*)d_in[26];
    const float* att1_b   = (const float*)d_in[27];
    const float* att2_W   = (const float*)d_in[28];
    const float* out_W    = (const float*)d_in[29];
    const float* out_b    = (const float*)d_in[30];
    float* out = (float*)d_out;

    float *hlast, *ssrc, *sdst, *hatt, *hfc, *zb, *rb;
    cudaGetSymbolAddress((void**)&hlast, g_hlast);
    cudaGetSymbolAddress((void**)&ssrc,  g_ssrc);
    cudaGetSymbolAddress((void**)&sdst,  g_sdst);
    cudaGetSymbolAddress((void**)&hatt,  g_hatt);
    cudaGetSymbolAddress((void**)&hfc,   g_hfc);
    cudaGetSymbolAddress((void**)&zb,    g_z);
    cudaGetSymbolAddress((void**)&rb,    g_r);

    // smem floats: DIN*192 + 3*12288 + 512 + 2*SPB*64 + SPB*DIN + WARPS*512
    // ENC: DIN=6, WARPS=9, SPB=72  -> 1152+36864+512+9216+432+4608 = 52784
    // AL : DIN=64, WARPS=4, SPB=32 -> 12288+36864+512+4096+2048+2048 = 57856
    const int ENC_SMEM = 52784 * 4;   // 211136
    const int AL_SMEM  = 57856 * 4;   // 231424
    cudaFuncSetAttribute((const void*)gru2q_kernel<6, false, 9>,
                         cudaFuncAttributeMaxDynamicSharedMemorySize, ENC_SMEM);
    cudaFuncSetAttribute((const void*)gru2q_kernel<64, true, 4>,
                         cudaFuncAttributeMaxDynamicSharedMemorySize, AL_SMEM);

    // 1) encoder: 2-layer GRU, N=10240, T=60 -> hlast (143 blocks = 1 wave)
    gru2q_kernel<6, false, 9><<<143, 288, ENC_SMEM>>>(
        x, rWih0, rWhh0, rbih0, rbhh0, rWih1, rWhh1, rbih1, rbhh1, hlast, 10240, 60);

    // 2) trans projection + rank-1 scores
    trans_score_kernel<<<40, 256>>>(hlast, trans_W, trans_b, a_vec, ssrc, sdst, 10240);

    // 3) per-group dense attention + residual
    gat_att_kernel<<<160, 256>>>(hlast, ssrc, sdst, hatt);

    // 4) fc
    fc_kernel<<<40, 256>>>(hatt, fc_W, fc_b, hfc, 10240);

    // 5) z = tanh(permuted hfc @ al_in_W.T + b)
    z_kernel<<<40, 256>>>(hfc, al_in_W, al_in_b, zb);

    // 6) ALSTM 2-layer GRU over K=20, batch 512, store all timesteps
    gru2q_kernel<64, true, 4><<<16, 128, AL_SMEM>>>(
        zb, aWih0, aWhh0, abih0, abhh0, aWih1, aWhh1, abih1, abhh1, rb, 512, 20);

    // 7) ALSTM attention head -> alstm_out (out[0:512])
    alstm_head_kernel<<<64, 256>>>(rb, att1_W, att1_b, att2_W, out_W, out_b, out);

    // 8) pred head -> out[512:1024]
    pred_kernel<<<2, 256>>>(hfc, fco_W, fco_b, out);
}

// round 6
// speedup vs baseline: 1.0256x; 1.0256x over previous
#include <cuda_runtime.h>
#include <cstdint>

#define DFI __device__ __forceinline__
typedef unsigned long long u64;

DFI float fsig(float x)  { return __fdividef(1.f, 1.f + __expf(-x)); }
DFI float ftanh(float x) { float e = __expf(2.f * x); return 1.f - __fdividef(2.f, e + 1.f); }
DFI float lrelu(float x) { return x > 0.f ? x : 0.01f * x; }

DFI u64 lds64(const float* p) { return *reinterpret_cast<const u64*>(p); }
DFI u64 pk0(float lo) { u64 r; asm("mov.b64 %0,{%1,%2};" : "=l"(r) : "f"(lo), "f"(0.f)); return r; }
DFI float red2(u64 v) { float lo, hi; asm("mov.b64 {%0,%1},%2;" : "=f"(lo), "=f"(hi) : "l"(v)); return lo + hi; }
DFI u64 ffma2(u64 a, u64 b, u64 c) { u64 d; asm("fma.rn.f32x2 %0,%1,%2,%3;" : "=l"(d) : "l"(a), "l"(b), "l"(c)); return d; }

// ---------------- scratch (no dynamic allocation allowed) ----------------
__device__ float g_hlast[10240 * 64];
__device__ float g_ssrc[10240];
__device__ float g_sdst[10240];
__device__ float g_hatt[10240 * 64];
__device__ float g_hfc[10240 * 64];
__device__ float g_z[512 * 20 * 64];
__device__ float g_r[512 * 20 * 64];

// =========================================================================
// Fused 2-layer GRU. 8 seqs/warp, NO gate-split: all 8 gate accumulators per
// seq live in registers (128 regs of accs). Single reduction pass per matrix
// -> each h vector read once. Weights quad-packed in smem:
//   wq[k4*768 + 4*o + q] = W[o][4*k4+q]   (LDS.128, 16B lane stride, no
//   conflicts). Data h rows contiguous -> broadcast LDS.128.
// Lane owns outputs o = lane, lane+32 per gate (r,z,n).
// =========================================================================
template <int DIN, bool STORE_ALL, int WARPS>
__global__ void __launch_bounds__(WARPS * 32, 1) gru2r_kernel(
    const float* __restrict__ X,
    const float* __restrict__ Wih0, const float* __restrict__ Whh0,
    const float* __restrict__ bih0, const float* __restrict__ bhh0,
    const float* __restrict__ Wih1, const float* __restrict__ Whh1,
    const float* __restrict__ bih1, const float* __restrict__ bhh1,
    float* __restrict__ OUT, int N, int T)
{
    extern __shared__ float sm[];
    constexpr int SPB = WARPS * 8;
    float* wih0 = sm;                       // DIN*192 (pair-pack if DIN==6, quad if 64)
    float* whh0 = wih0 + DIN * 192;         // 12288
    float* wih1 = whh0 + 12288;             // 12288
    float* whh1 = wih1 + 12288;             // 12288
    float* sb   = whh1 + 12288;             // 512
    float* sh0  = sb + 512;                 // SPB*64
    float* sh1  = sh0 + SPB * 64;           // SPB*64
    float* sx   = sh1 + SPB * 64;           // SPB*DIN

    const int tid = threadIdx.x, nth = WARPS * 32;
    if constexpr (DIN == 6) {
        for (int i = tid; i < 3 * 192; i += nth) {
            int k2 = i / 192, o = i - k2 * 192;
            wih0[k2 * 384 + 2 * o]     = Wih0[o * 6 + 2 * k2];
            wih0[k2 * 384 + 2 * o + 1] = Wih0[o * 6 + 2 * k2 + 1];
        }
    } else {
        for (int i = tid; i < 16 * 192; i += nth) {
            int k4 = i / 192, o = i - k4 * 192;
#pragma unroll
            for (int q = 0; q < 4; q++)
                wih0[k4 * 768 + 4 * o + q] = Wih0[o * 64 + 4 * k4 + q];
        }
    }
    for (int i = tid; i < 16 * 192; i += nth) {
        int k4 = i / 192, o = i - k4 * 192;
        int dst = k4 * 768 + 4 * o, src = o * 64 + 4 * k4;
#pragma unroll
        for (int q = 0; q < 4; q++) {
            whh0[dst + q] = Whh0[src + q];
            wih1[dst + q] = Wih1[src + q];
            whh1[dst + q] = Whh1[src + q];
        }
    }
    for (int i = tid; i < 128; i += nth) { sb[i] = bih0[i] + bhh0[i]; sb[256 + i] = bih1[i] + bhh1[i]; }
    for (int i = tid; i < 64; i += nth) {
        sb[128 + i] = bih0[128 + i]; sb[192 + i] = bhh0[128 + i];
        sb[384 + i] = bih1[128 + i]; sb[448 + i] = bhh1[128 + i];
    }
    for (int i = tid; i < SPB * 64; i += nth) { sh0[i] = 0.f; sh1[i] = 0.f; }
    __syncthreads();

    const int w = tid >> 5, lane = tid & 31;
    const int sl = w * 8;
    const int sg = (int)blockIdx.x * SPB + sl;
    if (sg >= N) return;   // whole-warp exit (N % 8 == 0, sg % 8 == 0)

    int qf[6];             // quad float offsets for the 6 owned output cols
#pragma unroll
    for (int j = 0; j < 6; j++) qf[j] = 4 * (lane + ((j & 1) << 5) + ((j >> 1) << 6));

    float* sxw  = sx + sl * DIN;
    float* sh0w = sh0 + sl * 64;
    float* sh1w = sh1 + sl * 64;
    const float* Xb = X + (long long)sg * T * DIN;

    for (int t = 0; t < T; ++t) {
        for (int i = lane; i < 8 * DIN; i += 32) {
            int s = i / DIN, d = i - s * DIN;
            sxw[i] = Xb[(long long)s * T * DIN + t * DIN + d];
        }
        __syncwarp();

        u64 ar[8][2], az[8][2], axn[8][2], ahn[8][2];

        // =========================== LAYER 0 ===========================
#pragma unroll
        for (int s = 0; s < 8; s++)
#pragma unroll
            for (int u = 0; u < 2; u++) {
                ar[s][u]  = pk0(sb[lane + (u << 5)]);
                az[s][u]  = pk0(sb[64 + lane + (u << 5)]);
                axn[s][u] = pk0(sb[128 + lane + (u << 5)]);
                ahn[s][u] = pk0(sb[192 + lane + (u << 5)]);
            }
        // x part
        if constexpr (DIN == 6) {
#pragma unroll
            for (int k2 = 0; k2 < 3; k2++) {
                const float* wb = wih0 + k2 * 384;
                u64 wv[6];
#pragma unroll
                for (int j = 0; j < 6; j++) wv[j] = lds64(wb + (qf[j] >> 1));
#pragma unroll
                for (int s = 0; s < 8; s++) {
                    u64 x2 = lds64(sxw + s * 6 + 2 * k2);
                    ar[s][0]  = ffma2(wv[0], x2, ar[s][0]);
                    ar[s][1]  = ffma2(wv[1], x2, ar[s][1]);
                    az[s][0]  = ffma2(wv[2], x2, az[s][0]);
                    az[s][1]  = ffma2(wv[3], x2, az[s][1]);
                    axn[s][0] = ffma2(wv[4], x2, axn[s][0]);
                    axn[s][1] = ffma2(wv[5], x2, axn[s][1]);
                }
            }
        } else {
#pragma unroll 1
            for (int k4 = 0; k4 < 16; k4++) {
                const float* wb = wih0 + k4 * 768;
                ulonglong2 wv[6];
#pragma unroll
                for (int j = 0; j < 6; j++) wv[j] = *reinterpret_cast<const ulonglong2*>(wb + qf[j]);
#pragma unroll
                for (int s = 0; s < 8; s++) {
                    ulonglong2 d2 = *reinterpret_cast<const ulonglong2*>(sxw + s * 64 + 4 * k4);
                    ar[s][0]  = ffma2(wv[0].x, d2.x, ar[s][0]);  ar[s][0]  = ffma2(wv[0].y, d2.y, ar[s][0]);
                    ar[s][1]  = ffma2(wv[1].x, d2.x, ar[s][1]);  ar[s][1]  = ffma2(wv[1].y, d2.y, ar[s][1]);
                    az[s][0]  = ffma2(wv[2].x, d2.x, az[s][0]);  az[s][0]  = ffma2(wv[2].y, d2.y, az[s][0]);
                    az[s][1]  = ffma2(wv[3].x, d2.x, az[s][1]);  az[s][1]  = ffma2(wv[3].y, d2.y, az[s][1]);
                    axn[s][0] = ffma2(wv[4].x, d2.x, axn[s][0]); axn[s][0] = ffma2(wv[4].y, d2.y, axn[s][0]);
                    axn[s][1] = ffma2(wv[5].x, d2.x, axn[s][1]); axn[s][1] = ffma2(wv[5].y, d2.y, axn[s][1]);
                }
            }
        }
        // h part (-> r, z, hn)
#pragma unroll 1
        for (int k4 = 0; k4 < 16; k4++) {
            const float* wb = whh0 + k4 * 768;
            ulonglong2 wv[6];
#pragma unroll
            for (int j = 0; j < 6; j++) wv[j] = *reinterpret_cast<const ulonglong2*>(wb + qf[j]);
#pragma unroll
            for (int s = 0; s < 8; s++) {
                ulonglong2 d2 = *reinterpret_cast<const ulonglong2*>(sh0w + s * 64 + 4 * k4);
                ar[s][0]  = ffma2(wv[0].x, d2.x, ar[s][0]);  ar[s][0]  = ffma2(wv[0].y, d2.y, ar[s][0]);
                ar[s][1]  = ffma2(wv[1].x, d2.x, ar[s][1]);  ar[s][1]  = ffma2(wv[1].y, d2.y, ar[s][1]);
                az[s][0]  = ffma2(wv[2].x, d2.x, az[s][0]);  az[s][0]  = ffma2(wv[2].y, d2.y, az[s][0]);
                az[s][1]  = ffma2(wv[3].x, d2.x, az[s][1]);  az[s][1]  = ffma2(wv[3].y, d2.y, az[s][1]);
                ahn[s][0] = ffma2(wv[4].x, d2.x, ahn[s][0]); ahn[s][0] = ffma2(wv[4].y, d2.y, ahn[s][0]);
                ahn[s][1] = ffma2(wv[5].x, d2.x, ahn[s][1]); ahn[s][1] = ffma2(wv[5].y, d2.y, ahn[s][1]);
            }
        }
        __syncwarp();
#pragma unroll
        for (int s = 0; s < 8; s++)
#pragma unroll
            for (int u = 0; u < 2; u++) {
                float r = fsig(red2(ar[s][u]));
                float z = fsig(red2(az[s][u]));
                float n = ftanh(fmaf(r, red2(ahn[s][u]), red2(axn[s][u])));
                int hi = s * 64 + lane + (u << 5);
                float hold = sh0w[hi];
                sh0w[hi] = (1.f - z) * n + z * hold;
            }
        __syncwarp();

        // =========================== LAYER 1 ===========================
#pragma unroll
        for (int s = 0; s < 8; s++)
#pragma unroll
            for (int u = 0; u < 2; u++) {
                ar[s][u]  = pk0(sb[256 + lane + (u << 5)]);
                az[s][u]  = pk0(sb[320 + lane + (u << 5)]);
                axn[s][u] = pk0(sb[384 + lane + (u << 5)]);
                ahn[s][u] = pk0(sb[448 + lane + (u << 5)]);
            }
        // ih part (input = new sh0) -> r, z, xn
#pragma unroll 1
        for (int k4 = 0; k4 < 16; k4++) {
            const float* wb = wih1 + k4 * 768;
            ulonglong2 wv[6];
#pragma unroll
            for (int j = 0; j < 6; j++) wv[j] = *reinterpret_cast<const ulonglong2*>(wb + qf[j]);
#pragma unroll
            for (int s = 0; s < 8; s++) {
                ulonglong2 d2 = *reinterpret_cast<const ulonglong2*>(sh0w + s * 64 + 4 * k4);
                ar[s][0]  = ffma2(wv[0].x, d2.x, ar[s][0]);  ar[s][0]  = ffma2(wv[0].y, d2.y, ar[s][0]);
                ar[s][1]  = ffma2(wv[1].x, d2.x, ar[s][1]);  ar[s][1]  = ffma2(wv[1].y, d2.y, ar[s][1]);
                az[s][0]  = ffma2(wv[2].x, d2.x, az[s][0]);  az[s][0]  = ffma2(wv[2].y, d2.y, az[s][0]);
                az[s][1]  = ffma2(wv[3].x, d2.x, az[s][1]);  az[s][1]  = ffma2(wv[3].y, d2.y, az[s][1]);
                axn[s][0] = ffma2(wv[4].x, d2.x, axn[s][0]); axn[s][0] = ffma2(wv[4].y, d2.y, axn[s][0]);
                axn[s][1] = ffma2(wv[5].x, d2.x, axn[s][1]); axn[s][1] = ffma2(wv[5].y, d2.y, axn[s][1]);
            }
        }
        // hh part -> r, z, hn
#pragma unroll 1
        for (int k4 = 0; k4 < 16; k4++) {
            const float* wb = whh1 + k4 * 768;
            ulonglong2 wv[6];
#pragma unroll
            for (int j = 0; j < 6; j++) wv[j] = *reinterpret_cast<const ulonglong2*>(wb + qf[j]);
#pragma unroll
            for (int s = 0; s < 8; s++) {
                ulonglong2 d2 = *reinterpret_cast<const ulonglong2*>(sh1w + s * 64 + 4 * k4);
                ar[s][0]  = ffma2(wv[0].x, d2.x, ar[s][0]);  ar[s][0]  = ffma2(wv[0].y, d2.y, ar[s][0]);
                ar[s][1]  = ffma2(wv[1].x, d2.x, ar[s][1]);  ar[s][1]  = ffma2(wv[1].y, d2.y, ar[s][1]);
                az[s][0]  = ffma2(wv[2].x, d2.x, az[s][0]);  az[s][0]  = ffma2(wv[2].y, d2.y, az[s][0]);
                az[s][1]  = ffma2(wv[3].x, d2.x, az[s][1]);  az[s][1]  = ffma2(wv[3].y, d2.y, az[s][1]);
                ahn[s][0] = ffma2(wv[4].x, d2.x, ahn[s][0]); ahn[s][0] = ffma2(wv[4].y, d2.y, ahn[s][0]);
                ahn[s][1] = ffma2(wv[5].x, d2.x, ahn[s][1]); ahn[s][1] = ffma2(wv[5].y, d2.y, ahn[s][1]);
            }
        }
        __syncwarp();
#pragma unroll
        for (int s = 0; s < 8; s++)
#pragma unroll
            for (int u = 0; u < 2; u++) {
                float r = fsig(red2(ar[s][u]));
                float z = fsig(red2(az[s][u]));
                float n = ftanh(fmaf(r, red2(ahn[s][u]), red2(axn[s][u])));
                int hi = s * 64 + lane + (u << 5);
                float hold = sh1w[hi];
                float hnew = (1.f - z) * n + z * hold;
                sh1w[hi] = hnew;
                if (STORE_ALL) OUT[((long long)(sg + s) * T + t) * 64 + lane + (u << 5)] = hnew;
            }
        __syncwarp();
    }
    if (!STORE_ALL) {
#pragma unroll
        for (int s = 0; s < 8; s++)
#pragma unroll
            for (int u = 0; u < 2; u++)
                OUT[(long long)(sg + s) * 64 + lane + (u << 5)] = sh1w[s * 64 + lane + (u << 5)];
    }
}

// =========================================================================
// xp = h @ trans_W.T + trans_b ; s_dst = xp @ a[:64] ; s_src = xp @ a[64:]
// =========================================================================
__global__ void trans_score_kernel(const float* __restrict__ H,
    const float* __restrict__ W, const float* __restrict__ b,
    const float* __restrict__ a, float* __restrict__ ssrc,
    float* __restrict__ sdst, int Nrows)
{
    __shared__ float sW[4096], sbv[64], sad[64], sas[64];
    for (int i = threadIdx.x; i < 4096; i += blockDim.x) sW[i] = W[i];
    for (int i = threadIdx.x; i < 64; i += blockDim.x) { sbv[i] = b[i]; sad[i] = a[i]; sas[i] = a[64 + i]; }
    __syncthreads();
    for (int row = blockIdx.x * blockDim.x + threadIdx.x; row < Nrows; row += gridDim.x * blockDim.x) {
        float h[64];
        const float4* hp = (const float4*)(H + (long long)row * 64);
#pragma unroll
        for (int q = 0; q < 16; q++) { float4 v = hp[q]; h[4*q] = v.x; h[4*q+1] = v.y; h[4*q+2] = v.z; h[4*q+3] = v.w; }
        float sd = 0.f, ss = 0.f;
#pragma unroll 4
        for (int o = 0; o < 64; o++) {
            float acc = sbv[o];
#pragma unroll
            for (int k = 0; k < 64; k++) acc = fmaf(h[k], sW[o * 64 + k], acc);
            sd = fmaf(acc, sad[o], sd);
            ss = fmaf(acc, sas[o], ss);
        }
        sdst[row] = sd; ssrc[row] = ss;
    }
}

// =========================================================================
// Dense per-group GAT: out[i] = softmax_j(lrelu(ssrc[i]+sdst[j])) @ h + h[i]
// =========================================================================
__global__ void gat_att_kernel(const float* __restrict__ Hin,
    const float* __restrict__ ssrc, const float* __restrict__ sdst,
    float* __restrict__ Hout)
{
    __shared__ float sd[512];
    __shared__ float se[8][512];
    const int g = blockIdx.x >> 3, chunk = blockIdx.x & 7;
    for (int i = threadIdx.x; i < 512; i += blockDim.x) sd[i] = sdst[g * 512 + i];
    __syncthreads();
    const int w = threadIdx.x >> 5, lane = threadIdx.x & 31;
    const float* Hg = Hin + (long long)g * 512 * 64;
    for (int rr = 0; rr < 8; ++rr) {
        const int i = chunk * 64 + w * 8 + rr;
        const float si = ssrc[g * 512 + i];
        float m = -1e30f, sc[16];
#pragma unroll
        for (int jj = 0; jj < 16; jj++) {
            float v = lrelu(si + sd[lane + (jj << 5)]);
            sc[jj] = v; m = fmaxf(m, v);
        }
#pragma unroll
        for (int off = 16; off; off >>= 1) m = fmaxf(m, __shfl_xor_sync(~0u, m, off));
        float ssum = 0.f;
#pragma unroll
        for (int jj = 0; jj < 16; jj++) {
            float e = __expf(sc[jj] - m);
            se[w][lane + (jj << 5)] = e; ssum += e;
        }
#pragma unroll
        for (int off = 16; off; off >>= 1) ssum += __shfl_xor_sync(~0u, ssum, off);
        __syncwarp();
        float2 acc = make_float2(0.f, 0.f);
        const int c = lane << 1;
#pragma unroll 4
        for (int j = 0; j < 512; j++) {
            float e = se[w][j];
            float2 hv = *(const float2*)(Hg + j * 64 + c);
            acc.x = fmaf(e, hv.x, acc.x);
            acc.y = fmaf(e, hv.y, acc.y);
        }
        float inv = __fdividef(1.f, ssum);
        float2 hi = *(const float2*)(Hg + i * 64 + c);
        float2 res; res.x = fmaf(acc.x, inv, hi.x); res.y = fmaf(acc.y, inv, hi.y);
        *(float2*)(Hout + ((long long)g * 512 + i) * 64 + c) = res;
        __syncwarp();
    }
}

// ============================ fc: 64x64 linear ===========================
__global__ void fc_kernel(const float* __restrict__ IN, const float* __restrict__ W,
                          const float* __restrict__ b, float* __restrict__ O, int Nrows)
{
    __shared__ float sW[4096], sb2[64];
    for (int i = threadIdx.x; i < 4096; i += blockDim.x) sW[i] = W[i];
    for (int i = threadIdx.x; i < 64; i += blockDim.x) sb2[i] = b[i];
    __syncthreads();
    for (int row = blockIdx.x * blockDim.x + threadIdx.x; row < Nrows; row += gridDim.x * blockDim.x) {
        float h[64];
        const float4* hp = (const float4*)(IN + (long long)row * 64);
#pragma unroll
        for (int q = 0; q < 16; q++) { float4 v = hp[q]; h[4*q] = v.x; h[4*q+1] = v.y; h[4*q+2] = v.z; h[4*q+3] = v.w; }
        float* op = O + (long long)row * 64;
#pragma unroll 2
        for (int o = 0; o < 64; o++) {
            float acc = sb2[o];
#pragma unroll
            for (int k = 0; k < 64; k++) acc = fmaf(h[k], sW[o * 64 + k], acc);
            op[o] = acc;
        }
    }
}

// ============= z = tanh(permute(hfc) @ al_in_W.T + al_in_b) ==============
__global__ void z_kernel(const float* __restrict__ Hfc, const float* __restrict__ W,
                         const float* __restrict__ b, float* __restrict__ Z)
{
    __shared__ float sW[4096], sb2[64];
    for (int i = threadIdx.x; i < 4096; i += blockDim.x) sW[i] = W[i];
    for (int i = threadIdx.x; i < 64; i += blockDim.x) sb2[i] = b[i];
    __syncthreads();
    int r = blockIdx.x * blockDim.x + threadIdx.x;
    if (r >= 512 * 20) return;
    int i = r / 20, k = r - i * 20;
    const float* hp = Hfc + (long long)(k * 512 + i) * 64;
    float h[64];
#pragma unroll
    for (int q = 0; q < 16; q++) { float4 v = ((const float4*)hp)[q]; h[4*q] = v.x; h[4*q+1] = v.y; h[4*q+2] = v.z; h[4*q+3] = v.w; }
    float* op = Z + (long long)r * 64;
#pragma unroll 2
    for (int o = 0; o < 64; o++) {
        float acc = sb2[o];
#pragma unroll
        for (int kk = 0; kk < 64; kk++) acc = fmaf(h[kk], sW[o * 64 + kk], acc);
        op[o] = ftanh(acc);
    }
}

// ======================= ALSTM attention head ============================
__global__ void alstm_head_kernel(const float* __restrict__ R,
    const float* __restrict__ W1, const float* __restrict__ b1,
    const float* __restrict__ W2, const float* __restrict__ Wout,
    const float* __restrict__ bout, float* __restrict__ outv)
{
    __shared__ float sW1t[64 * 32], sb1[32], sW2[32], sWo[128];
    __shared__ float sr[8][64], ssk[8][20];
    for (int i = threadIdx.x; i < 2048; i += blockDim.x) { int d = i >> 5, o = i & 31; sW1t[i] = W1[o * 64 + d]; }
    if (threadIdx.x < 32) { sb1[threadIdx.x] = b1[threadIdx.x]; sW2[threadIdx.x] = W2[threadIdx.x]; }
    for (int i = threadIdx.x; i < 128; i += blockDim.x) sWo[i] = Wout[i];
    __syncthreads();
    const int w = threadIdx.x >> 5, lane = threadIdx.x & 31;
    const int i = blockIdx.x * 8 + w;
    const float* Ri = R + (long long)i * 20 * 64;
    for (int k = 0; k < 20; k++) {
        sr[w][lane] = Ri[k * 64 + lane];
        sr[w][lane + 32] = Ri[k * 64 + lane + 32];
        __syncwarp();
        float acc = sb1[lane];
#pragma unroll
        for (int d = 0; d < 64; d++) acc = fmaf(sr[w][d], sW1t[(d << 5) + lane], acc);
        float p = ftanh(acc) * sW2[lane];
#pragma unroll
        for (int off = 16; off; off >>= 1) p += __shfl_xor_sync(~0u, p, off);
        if (lane == 0) ssk[w][k] = p;
        __syncwarp();
    }
    float m = -1e30f;
    for (int k = 0; k < 20; k++) m = fmaxf(m, ssk[w][k]);
    float ssum = 0.f;
    for (int k = 0; k < 20; k++) ssum += __expf(ssk[w][k] - m);
    float inv = __fdividef(1.f, ssum);
    float accf = 0.f;
    for (int k = 0; k < 20; k++) {
        float ak = __expf(ssk[w][k] - m) * inv;
        float r1 = Ri[k * 64 + lane], r2 = Ri[k * 64 + lane + 32];
        accf = fmaf(ak * r1, sWo[64 + lane], accf);
        accf = fmaf(ak * r2, sWo[96 + lane], accf);
    }
    {
        float r1 = Ri[19 * 64 + lane], r2 = Ri[19 * 64 + lane + 32];
        accf = fmaf(r1, sWo[lane], accf);
        accf = fmaf(r2, sWo[32 + lane], accf);
    }
#pragma unroll
    for (int off = 16; off; off >>= 1) accf += __shfl_xor_sync(~0u, accf, off);
    if (lane == 0) outv[i] = accf + bout[0];
}

// ============ pred = lrelu(hfc[group 19]) @ fco_W.T + fco_b ==============
__global__ void pred_kernel(const float* __restrict__ Hfc, const float* __restrict__ fcoW,
                            const float* __restrict__ fcob, float* __restrict__ outv)
{
    __shared__ float sw[64];
    if (threadIdx.x < 64) sw[threadIdx.x] = fcoW[threadIdx.x];
    __syncthreads();
    int i = blockIdx.x * blockDim.x + threadIdx.x;
    if (i < 512) {
        const float* hp = Hfc + (long long)(19 * 512 + i) * 64;
        float s = fcob[0];
#pragma unroll 8
        for (int c = 0; c < 64; c++) { float v = hp[c]; v = v > 0.f ? v : 0.01f * v; s = fmaf(v, sw[c], s); }
        outv[512 + i] = s;
    }
}

// =========================================================================
extern "C" void kernel_launch(void* const* d_in, const int* in_sizes, int n_in,
                              void* d_out, int out_size)
{
    const float* x        = (const float*)d_in[0];
    const float* rWih0    = (const float*)d_in[1];
    const float* rWhh0    = (const float*)d_in[2];
    const float* rbih0    = (const float*)d_in[3];
    const float* rbhh0    = (const float*)d_in[4];
    const float* rWih1    = (const float*)d_in[5];
    const float* rWhh1    = (const float*)d_in[6];
    const float* rbih1    = (const float*)d_in[7];
    const float* rbhh1    = (const float*)d_in[8];
    const float* trans_W  = (const float*)d_in[9];
    const float* trans_b  = (const float*)d_in[10];
    const float* a_vec    = (const float*)d_in[11];
    const float* fc_W     = (const float*)d_in[12];
    const float* fc_b     = (const float*)d_in[13];
    const float* fco_W    = (const float*)d_in[14];
    const float* fco_b    = (const float*)d_in[15];
    const float* al_in_W  = (const float*)d_in[16];
    const float* al_in_b  = (const float*)d_in[17];
    const float* aWih0    = (const float*)d_in[18];
    const float* aWhh0    = (const float*)d_in[19];
    const float* abih0    = (const float*)d_in[20];
    const float* abhh0    = (const float*)d_in[21];
    const float* aWih1    = (const float*)d_in[22];
    const float* aWhh1    = (const float*)d_in[23];
    const float* abih1    = (const float*)d_in[24];
    const float* abhh1    = (const float*)d_in[25];
    const float* att1_W   = (const float*)d_in[26];
    const float* att1_b   = (const float*)d_in[27];
    const float* att2_W   = (const float*)d_in[28];
    const float* out_W    = (const float*)d_in[29];
    const float* out_b    = (const float*)d_in[30];
    float* out = (float*)d_out;

    float *hlast, *ssrc, *sdst, *hatt, *hfc, *zb, *rb;
    cudaGetSymbolAddress((void**)&hlast, g_hlast);
    cudaGetSymbolAddress((void**)&ssrc,  g_ssrc);
    cudaGetSymbolAddress((void**)&sdst,  g_sdst);
    cudaGetSymbolAddress((void**)&hatt,  g_hatt);
    cudaGetSymbolAddress((void**)&hfc,   g_hfc);
    cudaGetSymbolAddress((void**)&zb,    g_z);
    cudaGetSymbolAddress((void**)&rb,    g_r);

    // smem floats: DIN*192 + 3*12288 + 512 + 2*SPB*64 + SPB*DIN
    // ENC: DIN=6,  WARPS=9, SPB=72 -> 1152+36864+512+9216+432  = 48176
    // AL : DIN=64, WARPS=4, SPB=32 -> 12288+36864+512+4096+2048 = 55808
    const int ENC_SMEM = 48176 * 4;   // 192704
    const int AL_SMEM  = 55808 * 4;   // 223232
    cudaFuncSetAttribute((const void*)gru2r_kernel<6, false, 9>,
                         cudaFuncAttributeMaxDynamicSharedMemorySize, ENC_SMEM);
    cudaFuncSetAttribute((const void*)gru2r_kernel<64, true, 4>,
                         cudaFuncAttributeMaxDynamicSharedMemorySize, AL_SMEM);

    // 1) encoder: 2-layer GRU, N=10240, T=60 -> hlast (143 blocks = 1 wave)
    gru2r_kernel<6, false, 9><<<143, 288, ENC_SMEM>>>(
        x, rWih0, rWhh0, rbih0, rbhh0, rWih1, rWhh1, rbih1, rbhh1, hlast, 10240, 60);

    // 2) trans projection + rank-1 scores
    trans_score_kernel<<<40, 256>>>(hlast, trans_W, trans_b, a_vec, ssrc, sdst, 10240);

    // 3) per-group dense attention + residual
    gat_att_kernel<<<160, 256>>>(hlast, ssrc, sdst, hatt);

    // 4) fc
    fc_kernel<<<40, 256>>>(hatt, fc_W, fc_b, hfc, 10240);

    // 5) z = tanh(permuted hfc @ al_in_W.T + b)
    z_kernel<<<40, 256>>>(hfc, al_in_W, al_in_b, zb);

    // 6) ALSTM 2-layer GRU over K=20, batch 512, store all timesteps
    gru2r_kernel<64, true, 4><<<16, 128, AL_SMEM>>>(
        zb, aWih0, aWhh0, abih0, abhh0, aWih1, aWhh1, abih1, abhh1, rb, 512, 20);

    // 7) ALSTM attention head -> alstm_out (out[0:512])
    alstm_head_kernel<<<64, 256>>>(rb, att1_W, att1_b, att2_W, out_W, out_b, out);

    // 8) pred head -> out[512:1024]
    pred_kernel<<<2, 256>>>(hfc, fco_W, fco_b, out);
}